// round 1
// baseline (speedup 1.0000x reference)
#include <cuda_runtime.h>

#define VX 64
#define NB 8
#define NP 32
#define PE 32
#define SHARP 100.0f
#define EPSF 1e-8f

// Block: one (batch b, row y). 256 threads = 64 pixels x 4 polygon-groups (8 polys each).
// Shared: precomputed edge data for all 32 polygons (1024 edges x 8 floats = 32KB).
__global__ __launch_bounds__(256) void extrusion_kernel(
    const float* __restrict__ polygons,   // [B][N][P][2]
    const float* __restrict__ attributes, // [B][4]
    const float* __restrict__ validity,   // [B][N]
    float* __restrict__ out)              // [B][V][V][V]
{
    __shared__ float sE[NP * PE * 8];     // per edge: x0,y0,ex,ey | inv_esq, sx, ylo, yhi
    __shared__ float sValid[NP];
    __shared__ float sPartial[4][VX];
    __shared__ float sComb[VX];

    const int b   = blockIdx.x >> 6;   // blockIdx.x / 64
    const int row = blockIdx.x & 63;   // y coordinate
    const int tid = threadIdx.x;

    // ---- Phase 1: precompute edge-invariant data into smem ----
    const float* poly_b = polygons + (size_t)b * NP * PE * 2;
    for (int i = tid; i < NP * PE; i += 256) {
        const int n  = i >> 5;
        const int e  = i & 31;
        const int e1 = (e + 1) & 31;
        const float x0 = poly_b[(n * PE + e ) * 2 + 0];
        const float y0 = poly_b[(n * PE + e ) * 2 + 1];
        const float x1 = poly_b[(n * PE + e1) * 2 + 0];
        const float y1 = poly_b[(n * PE + e1) * 2 + 1];
        const float ex = x1 - x0;
        const float ey = y1 - y0;
        const float inv_esq = 1.0f / (ex * ex + ey * ey + EPSF);
        const float sx      = ex * (1.0f / (ey + EPSF));   // (x1-x0)/(y1-y0+eps)
        float* d = sE + i * 8;
        d[0] = x0; d[1] = y0; d[2] = ex; d[3] = ey;
        d[4] = inv_esq; d[5] = sx;
        d[6] = fminf(y0, y1); d[7] = fmaxf(y0, y1);
    }
    if (tid < NP) sValid[tid] = validity[b * NP + tid];
    __syncthreads();

    // ---- Phase 2: SDF + sigmoid + max over this thread's 8 polygons ----
    const int   xi  = tid & 63;
    const int   grp = tid >> 6;            // 0..3
    const float px  = (float)xi  * (1.0f / 63.0f);
    const float py  = (float)row * (1.0f / 63.0f);

    float best = 0.0f;
    const int n_begin = grp * 8;
    for (int n = n_begin; n < n_begin + 8; n++) {
        if (sValid[n] < 0.5f) continue;    // invalid poly contributes 0 to the max
        float min_d2 = 3.4e38f;
        int   parity = 0;
        const float4* ep = (const float4*)(sE + n * PE * 8);
        #pragma unroll 8
        for (int e = 0; e < PE; e++) {
            const float4 a = ep[e * 2 + 0];   // x0, y0, ex, ey
            const float4 c = ep[e * 2 + 1];   // inv_esq, sx, ylo, yhi
            const float vx = px - a.x;
            const float vy = py - a.y;
            float t = (vx * a.z + vy * a.w) * c.x;
            t = fminf(fmaxf(t, 0.0f), 1.0f);
            const float dx = vx - t * a.z;
            const float dy = vy - t * a.w;
            const float d2 = dx * dx + dy * dy;
            min_d2 = fminf(min_d2, d2);
            // crossing test: (ylo <= py < yhi) && (inter_x > px)
            const float interx = a.x + c.y * (py - a.y);
            const bool cross = (c.z <= py) & (c.w > py) & (interx > px);
            parity ^= (int)cross;
        }
        const float dist = sqrtf(min_d2);
        const float sdf  = parity ? -dist : dist;
        const float mask = 1.0f / (1.0f + __expf(SHARP * sdf));
        best = fmaxf(best, mask);
    }
    sPartial[grp][xi] = best;
    __syncthreads();

    // ---- Phase 3: reduce 4 partials -> combined[x] for this row ----
    if (tid < VX) {
        sComb[tid] = fmaxf(fmaxf(sPartial[0][tid], sPartial[1][tid]),
                           fmaxf(sPartial[2][tid], sPartial[3][tid]));
    }
    __syncthreads();

    // ---- Phase 4: expand along z and store (coalesced float4) ----
    int h = (int)floorf(attributes[b * 4 + 0] * (float)VX);
    h = max(1, min(VX, h));

    const float4* comb4 = (const float4*)sComb;
    float* out_base = out + (size_t)b * VX * VX * VX + (size_t)row * VX;
    const float4 zero4 = make_float4(0.f, 0.f, 0.f, 0.f);
    // 64 z-levels x 16 float4 per row = 1024 float4 stores per block
    for (int i = tid; i < VX * 16; i += 256) {
        const int z  = i >> 4;
        const int xq = i & 15;
        float4* dst = (float4*)(out_base + (size_t)z * VX * VX);
        dst[xq] = (z < h) ? comb4[xq] : zero4;
    }
}

extern "C" void kernel_launch(void* const* d_in, const int* in_sizes, int n_in,
                              void* d_out, int out_size) {
    const float* polygons   = (const float*)d_in[0];
    const float* attributes = (const float*)d_in[1];
    const float* validity   = (const float*)d_in[2];
    float* out = (float*)d_out;
    (void)in_sizes; (void)n_in; (void)out_size;

    dim3 grid(NB * VX);   // 512 blocks: (b, row)
    dim3 block(256);
    extrusion_kernel<<<grid, block>>>(polygons, attributes, validity, out);
}

// round 2
// speedup vs baseline: 1.0807x; 1.0807x over previous
#include <cuda_runtime.h>
#include <float.h>

#define VX 64
#define NB 8
#define NP 32
#define PE 32
#define SHARP 100.0f
#define EPSF 1e-8f
#define NTHREADS 512
#define NGRP 8                    // polygon groups per block
#define POLY_PER_GRP (NP / NGRP)  // 4

// Block: one (batch b, row y). 512 threads = 64 pixels x 8 polygon-groups (4 polys each).
// Per-block precompute folds ALL py-dependent terms into shared memory, so the
// 33.5M-iteration inner loop is pure per-pixel work: ~14 issue slots/edge.
__global__ __launch_bounds__(NTHREADS) void extrusion_kernel(
    const float* __restrict__ polygons,   // [B][N][P][2]
    const float* __restrict__ attributes, // [B][4]
    const float* __restrict__ validity,   // [B][N]
    float* __restrict__ out)              // [B][V][V][V]
{
    __shared__ float4 sA[NP * PE];        // x0, ex, ey, sy   (sy = vy*ey)
    __shared__ float4 sB[NP * PE];        // inv_esq, vy, cxthr, pad
    __shared__ float  sValid[NP];
    __shared__ float  sPartial[NGRP][VX];
    __shared__ float  sComb[VX];

    const int b   = blockIdx.x >> 6;
    const int row = blockIdx.x & 63;
    const int tid = threadIdx.x;
    const float py = (float)row * (1.0f / 63.0f);

    // ---- Phase 1: per-block edge precompute (py folded in) ----
    const float* poly_b = polygons + (size_t)b * NP * PE * 2;
    for (int i = tid; i < NP * PE; i += NTHREADS) {
        const int n  = i >> 5;
        const int e  = i & 31;
        const int e1 = (e + 1) & 31;
        const float x0 = poly_b[(n * PE + e ) * 2 + 0];
        const float y0 = poly_b[(n * PE + e ) * 2 + 1];
        const float x1 = poly_b[(n * PE + e1) * 2 + 0];
        const float y1 = poly_b[(n * PE + e1) * 2 + 1];
        const float ex = x1 - x0;
        const float ey = y1 - y0;
        const float inv_esq = 1.0f / (ex * ex + ey * ey + EPSF);
        const float vy = py - y0;
        const float sy = vy * ey;
        // crossing: y_crosses <=> min(y0,y1) <= py < max(y0,y1)
        const bool ycr = (fminf(y0, y1) <= py) && (fmaxf(y0, y1) > py);
        const float interx = x0 + ex * (vy / (ey + EPSF));
        const float cxthr = ycr ? interx : -FLT_MAX;
        sA[i] = make_float4(x0, ex, ey, sy);
        sB[i] = make_float4(inv_esq, vy, cxthr, 0.0f);
    }
    if (tid < NP) sValid[tid] = validity[b * NP + tid];
    __syncthreads();

    // ---- Phase 2: SDF + sigmoid + max over this thread's polygons ----
    const int   xi  = tid & 63;
    const int   grp = tid >> 6;           // 0..7
    const float px  = (float)xi * (1.0f / 63.0f);

    float best = 0.0f;
    const int n_begin = grp * POLY_PER_GRP;
    #pragma unroll
    for (int k = 0; k < POLY_PER_GRP; k++) {
        const int n = n_begin + k;
        if (sValid[n] < 0.5f) continue;   // uniform across warp (same grp)
        float min_d2 = FLT_MAX;
        int   par = 0;
        const float4* A4 = sA + n * PE;
        const float4* B4 = sB + n * PE;
        #pragma unroll
        for (int e = 0; e < PE; e++) {
            const float4 a = A4[e];       // x0, ex, ey, sy
            const float4 c = B4[e];       // inv, vy, cxthr, -
            const float vx = px - a.x;
            float t = fmaf(vx, a.y, a.w) * c.x;   // (vx*ex + vy*ey) * inv
            t = fminf(fmaxf(t, 0.0f), 1.0f);
            const float dx = fmaf(-t, a.y, vx);
            const float dy = fmaf(-t, a.z, c.y);
            const float d2 = fmaf(dy, dy, dx * dx);
            min_d2 = fminf(min_d2, d2);
            par ^= (c.z > px);
        }
        const float dist = sqrtf(min_d2);
        const float sdf  = par ? -dist : dist;
        const float mask = 1.0f / (1.0f + __expf(SHARP * sdf));
        best = fmaxf(best, mask);
    }
    sPartial[grp][xi] = best;
    __syncthreads();

    // ---- Phase 3: 8-way max reduce -> combined row ----
    if (tid < VX) {
        float m = sPartial[0][tid];
        #pragma unroll
        for (int g = 1; g < NGRP; g++) m = fmaxf(m, sPartial[g][tid]);
        sComb[tid] = m;
    }
    __syncthreads();

    // ---- Phase 4: expand along z, coalesced float4 stores ----
    int h = (int)floorf(attributes[b * 4 + 0] * (float)VX);
    h = max(1, min(VX, h));

    const float4* comb4 = (const float4*)sComb;
    float* out_base = out + (size_t)b * VX * VX * VX + (size_t)row * VX;
    const float4 zero4 = make_float4(0.f, 0.f, 0.f, 0.f);
    #pragma unroll
    for (int i = tid; i < VX * 16; i += NTHREADS) {   // 2 iterations
        const int z  = i >> 4;
        const int xq = i & 15;
        float4* dst = (float4*)(out_base + (size_t)z * VX * VX);
        dst[xq] = (z < h) ? comb4[xq] : zero4;
    }
}

extern "C" void kernel_launch(void* const* d_in, const int* in_sizes, int n_in,
                              void* d_out, int out_size) {
    const float* polygons   = (const float*)d_in[0];
    const float* attributes = (const float*)d_in[1];
    const float* validity   = (const float*)d_in[2];
    float* out = (float*)d_out;
    (void)in_sizes; (void)n_in; (void)out_size;

    extrusion_kernel<<<NB * VX, NTHREADS>>>(polygons, attributes, validity, out);
}

// round 3
// speedup vs baseline: 1.2284x; 1.1367x over previous
#include <cuda_runtime.h>
#include <float.h>

#define VX 64
#define NB 8
#define NP 32
#define PE 32
#define SHARP 100.0f
#define EPSF 1e-8f
#define NTHREADS 256
#define NWARPS 8
#define POLY_PER_WARP (NP / NWARPS)   // 4

// Block: one (batch b, row y). 256 threads = 8 warps; warp g owns polygons
// [4g,4g+4). Each lane evaluates 2 pixels (x=lane, x=lane+32) so every
// broadcast LDS pair is amortized over 2 evaluations and gives 2 independent
// dependency chains for latency hiding.
__global__ __launch_bounds__(NTHREADS, 5) void extrusion_kernel(
    const float* __restrict__ polygons,   // [B][N][P][2]
    const float* __restrict__ attributes, // [B][4]
    const float* __restrict__ validity,   // [B][N]
    float* __restrict__ out)              // [B][V][V][V]
{
    __shared__ float4 sA[NP * PE];        // x0, ex, ey, sy  (sy = vy*ey)
    __shared__ float4 sB[NP * PE];        // inv_esq, vy, cxthr, pad
    __shared__ float  sValid[NP];
    __shared__ float  sPartial[NWARPS][VX];
    __shared__ float  sComb[VX];

    const int b   = blockIdx.x >> 6;
    const int row = blockIdx.x & 63;
    const int tid = threadIdx.x;
    const float py = (float)row * (1.0f / 63.0f);

    // ---- Phase 1: per-block edge precompute (all py-dependent terms folded) ----
    const float* poly_b = polygons + (size_t)b * NP * PE * 2;
    #pragma unroll
    for (int i = tid; i < NP * PE; i += NTHREADS) {
        const int n  = i >> 5;
        const int e  = i & 31;
        const int e1 = (e + 1) & 31;
        const float x0 = poly_b[(n * PE + e ) * 2 + 0];
        const float y0 = poly_b[(n * PE + e ) * 2 + 1];
        const float x1 = poly_b[(n * PE + e1) * 2 + 0];
        const float y1 = poly_b[(n * PE + e1) * 2 + 1];
        const float ex = x1 - x0;
        const float ey = y1 - y0;
        const float inv_esq = 1.0f / (ex * ex + ey * ey + EPSF);
        const float vy = py - y0;
        const float sy = vy * ey;
        const bool ycr = (fminf(y0, y1) <= py) && (fmaxf(y0, y1) > py);
        const float interx = x0 + ex * (vy / (ey + EPSF));
        const float cxthr = ycr ? interx : -FLT_MAX;
        sA[i] = make_float4(x0, ex, ey, sy);
        sB[i] = make_float4(inv_esq, vy, cxthr, 0.0f);
    }
    if (tid < NP) sValid[tid] = validity[b * NP + tid];
    __syncthreads();

    // ---- Phase 2: SDF + sigmoid + max, 2 pixels per lane ----
    const int lane = tid & 31;
    const int g    = tid >> 5;            // warp id = polygon group
    const float pxa = (float)lane        * (1.0f / 63.0f);
    const float pxb = (float)(lane + 32) * (1.0f / 63.0f);

    float best_a = 0.0f, best_b = 0.0f;
    #pragma unroll
    for (int k = 0; k < POLY_PER_WARP; k++) {
        const int n = g * POLY_PER_WARP + k;
        if (sValid[n] < 0.5f) continue;   // warp-uniform branch
        float min_a = FLT_MAX, min_b = FLT_MAX;
        int par_a = 0, par_b = 0;
        const float4* A4 = sA + n * PE;
        const float4* B4 = sB + n * PE;
        #pragma unroll 8
        for (int e = 0; e < PE; e++) {
            const float4 a = A4[e];       // x0, ex, ey, sy
            const float4 c = B4[e];       // inv, vy, cxthr, -
            const float vxa = pxa - a.x;
            const float vxb = pxb - a.x;
            float ta = fmaf(vxa, a.y, a.w) * c.x;
            float tb = fmaf(vxb, a.y, a.w) * c.x;
            ta = fminf(fmaxf(ta, 0.0f), 1.0f);
            tb = fminf(fmaxf(tb, 0.0f), 1.0f);
            const float dxa = fmaf(-ta, a.y, vxa);
            const float dxb = fmaf(-tb, a.y, vxb);
            const float dya = fmaf(-ta, a.z, c.y);
            const float dyb = fmaf(-tb, a.z, c.y);
            min_a = fminf(min_a, fmaf(dya, dya, dxa * dxa));
            min_b = fminf(min_b, fmaf(dyb, dyb, dxb * dxb));
            par_a ^= (c.z > pxa);
            par_b ^= (c.z > pxb);
        }
        const float da = sqrtf(min_a);
        const float db = sqrtf(min_b);
        const float sa = par_a ? -da : da;
        const float sb = par_b ? -db : db;
        best_a = fmaxf(best_a, __fdividef(1.0f, 1.0f + __expf(SHARP * sa)));
        best_b = fmaxf(best_b, __fdividef(1.0f, 1.0f + __expf(SHARP * sb)));
    }
    sPartial[g][lane]      = best_a;
    sPartial[g][lane + 32] = best_b;
    __syncthreads();

    // ---- Phase 3: 8-way max reduce -> combined row ----
    if (tid < VX) {
        float m = sPartial[0][tid];
        #pragma unroll
        for (int w = 1; w < NWARPS; w++) m = fmaxf(m, sPartial[w][tid]);
        sComb[tid] = m;
    }
    __syncthreads();

    // ---- Phase 4: expand along z, coalesced float4 stores ----
    int h = (int)floorf(attributes[b * 4 + 0] * (float)VX);
    h = max(1, min(VX, h));

    const float4* comb4 = (const float4*)sComb;
    float* out_base = out + (size_t)b * VX * VX * VX + (size_t)row * VX;
    const float4 zero4 = make_float4(0.f, 0.f, 0.f, 0.f);
    #pragma unroll
    for (int i = tid; i < VX * 16; i += NTHREADS) {   // 4 iterations
        const int z  = i >> 4;
        const int xq = i & 15;
        float4* dst = (float4*)(out_base + (size_t)z * VX * VX);
        dst[xq] = (z < h) ? comb4[xq] : zero4;
    }
}

extern "C" void kernel_launch(void* const* d_in, const int* in_sizes, int n_in,
                              void* d_out, int out_size) {
    const float* polygons   = (const float*)d_in[0];
    const float* attributes = (const float*)d_in[1];
    const float* validity   = (const float*)d_in[2];
    float* out = (float*)d_out;
    (void)in_sizes; (void)n_in; (void)out_size;

    extrusion_kernel<<<NB * VX, NTHREADS>>>(polygons, attributes, validity, out);
}

// round 5
// speedup vs baseline: 1.5778x; 1.2844x over previous
#include <cuda_runtime.h>
#include <float.h>

#define VX 64
#define NB 8
#define NP 32
#define PE 32
#define SHARP 100.0f
#define EPSF 1e-8f
#define NTHREADS 256
#define NWARPS 8

// Block: one (batch b, row y). 8 warps; VALID polygons are compacted into a
// list and dealt to warps round-robin (warp g takes compacted polys g, g+8,...)
// so the block-critical warp does ceil(V/8) polys instead of max-of-groups.
// Each lane evaluates 2 pixels (x=lane, x=lane+32): 2 indep chains per LDS pair.
// NOTE: every shared array that is reinterpreted as float4 is explicitly
// 16B-aligned (plain __shared__ float[] is only 4B-aligned -> LDS.128 trap).
__global__ __launch_bounds__(NTHREADS, 4) void extrusion_kernel(
    const float* __restrict__ polygons,   // [B][N][P][2]
    const float* __restrict__ attributes, // [B][4]
    const float* __restrict__ validity,   // [B][N]
    float* __restrict__ out)              // [B][V][V][V]
{
    __shared__ __align__(16) float4 sA[NP * PE];   // x0, exi, syi, cxthr
    __shared__ __align__(16) float4 sB[NP * PE];   // ex, ey, vy, pad
    __shared__ __align__(16) float  sPartial[NWARPS][VX];
    __shared__ __align__(16) float  sComb[VX];
    __shared__ int    sIdx[NP];           // compacted valid polygon indices
    __shared__ int    sV;                 // number of valid polygons

    const int b   = blockIdx.x >> 6;
    const int row = blockIdx.x & 63;
    const int tid = threadIdx.x;
    const float py = (float)row * (1.0f / 63.0f);

    // ---- Phase 1a: validity compaction (warp 0) ----
    if (tid < 32) {
        const bool valid = validity[b * NP + tid] >= 0.5f;
        const unsigned m = __ballot_sync(0xffffffffu, valid);
        if (valid) {
            const int pos = __popc(m & ((1u << tid) - 1u));
            sIdx[pos] = tid;
        }
        if (tid == 0) sV = __popc(m);
    }

    // ---- Phase 1b: per-block edge precompute (py folded in) ----
    const float* poly_b = polygons + (size_t)b * NP * PE * 2;
    #pragma unroll
    for (int i = tid; i < NP * PE; i += NTHREADS) {
        const int n  = i >> 5;
        const int e  = i & 31;
        const int e1 = (e + 1) & 31;
        const float x0 = poly_b[(n * PE + e ) * 2 + 0];
        const float y0 = poly_b[(n * PE + e ) * 2 + 1];
        const float x1 = poly_b[(n * PE + e1) * 2 + 0];
        const float y1 = poly_b[(n * PE + e1) * 2 + 1];
        const float ex = x1 - x0;
        const float ey = y1 - y0;
        const float inv = 1.0f / (ex * ex + ey * ey + EPSF);
        const float vy  = py - y0;
        const float exi = ex * inv;
        const float syi = (vy * ey) * inv;
        const bool ycr = (fminf(y0, y1) <= py) && (fmaxf(y0, y1) > py);
        const float interx = x0 + ex * (vy / (ey + EPSF));
        const float cxthr = ycr ? interx : -FLT_MAX;
        sA[i] = make_float4(x0, exi, syi, cxthr);
        sB[i] = make_float4(ex, ey, vy, 0.0f);
    }
    __syncthreads();

    // ---- Phase 2: SDF + sigmoid + max, 2 pixels per lane ----
    const int lane = tid & 31;
    const int g    = tid >> 5;
    const float pxa = (float)lane        * (1.0f / 63.0f);
    const float pxb = (float)(lane + 32) * (1.0f / 63.0f);
    const int nv = sV;

    float best_a = 0.0f, best_b = 0.0f;
    #pragma unroll 1
    for (int j = g; j < nv; j += NWARPS) {
        const int n = sIdx[j];
        float min_a = FLT_MAX, min_b = FLT_MAX;
        int par_a = 0, par_b = 0;
        const float4* A4 = sA + n * PE;
        const float4* B4 = sB + n * PE;
        #pragma unroll
        for (int e = 0; e < PE; e++) {
            const float4 a = A4[e];       // x0, exi, syi, cxthr
            const float4 c = B4[e];       // ex, ey, vy, -
            const float vxa = pxa - a.x;
            const float vxb = pxb - a.x;
            const float ta = __saturatef(fmaf(vxa, a.y, a.z));
            const float tb = __saturatef(fmaf(vxb, a.y, a.z));
            const float dxa = fmaf(-ta, c.x, vxa);
            const float dxb = fmaf(-tb, c.x, vxb);
            const float dya = fmaf(-ta, c.y, c.z);
            const float dyb = fmaf(-tb, c.y, c.z);
            min_a = fminf(min_a, fmaf(dya, dya, dxa * dxa));
            min_b = fminf(min_b, fmaf(dyb, dyb, dxb * dxb));
            par_a ^= (a.w > pxa);
            par_b ^= (a.w > pxb);
        }
        const float da = sqrtf(min_a);
        const float db = sqrtf(min_b);
        const float sa = par_a ? -da : da;
        const float sb = par_b ? -db : db;
        best_a = fmaxf(best_a, __fdividef(1.0f, 1.0f + __expf(SHARP * sa)));
        best_b = fmaxf(best_b, __fdividef(1.0f, 1.0f + __expf(SHARP * sb)));
    }
    sPartial[g][lane]      = best_a;
    sPartial[g][lane + 32] = best_b;
    __syncthreads();

    // ---- Phase 3: 8-way max reduce -> combined row ----
    if (tid < VX) {
        float m = sPartial[0][tid];
        #pragma unroll
        for (int w = 1; w < NWARPS; w++) m = fmaxf(m, sPartial[w][tid]);
        sComb[tid] = m;
    }
    __syncthreads();

    // ---- Phase 4: expand along z, coalesced float4 stores ----
    int h = (int)floorf(attributes[b * 4 + 0] * (float)VX);
    h = max(1, min(VX, h));

    const float4* comb4 = (const float4*)sComb;
    float* out_base = out + (size_t)b * VX * VX * VX + (size_t)row * VX;
    const float4 zero4 = make_float4(0.f, 0.f, 0.f, 0.f);
    #pragma unroll
    for (int i = tid; i < VX * 16; i += NTHREADS) {   // 4 iterations
        const int z  = i >> 4;
        const int xq = i & 15;
        float4* dst = (float4*)(out_base + (size_t)z * VX * VX);
        dst[xq] = (z < h) ? comb4[xq] : zero4;
    }
}

extern "C" void kernel_launch(void* const* d_in, const int* in_sizes, int n_in,
                              void* d_out, int out_size) {
    const float* polygons   = (const float*)d_in[0];
    const float* attributes = (const float*)d_in[1];
    const float* validity   = (const float*)d_in[2];
    float* out = (float*)d_out;
    (void)in_sizes; (void)n_in; (void)out_size;

    extrusion_kernel<<<NB * VX, NTHREADS>>>(polygons, attributes, validity, out);
}